// round 14
// baseline (speedup 1.0000x reference)
#include <cuda_runtime.h>
#include <cuda_fp16.h>
#include <math.h>
#include <stdint.h>

// ---------------------------------------------------------------------------
// Problem: D=512, H=8 (e=64), B=64 studies, N=131072 cells.
// Padded layout: row r = n*64 + g. max_n data-dependent; CAP upper bound.
// fp16 datapath everywhere except LN stats / softmax / pool accumulation.
// ---------------------------------------------------------------------------
#define CAP       2560
#define ROWS_CAP  (CAP * 64)   // 163840

__device__ int g_maxn;
__device__ int g_starts[65];
__device__ int g_counts[64];

__device__ __align__(128) __half g_Xh  [(size_t)ROWS_CAP * 512];
__device__ __align__(128) __half g_QKVh[(size_t)ROWS_CAP * 1536];
__device__ __align__(128) __half g_ATTh[(size_t)ROWS_CAP * 512];
__device__ __align__(128) __half g_TMPh[(size_t)ROWS_CAP * 512];
__device__ __align__(128) __half g_Y1h [(size_t)ROWS_CAP * 512];
__device__ __align__(128) __half g_HIDh[(size_t)ROWS_CAP * 1024];
__device__ __align__(128) __half g_Wh  [2097152];  // fp16 W_in | W_o | W1 | W2
__device__ float g_PART[16 * 64 * 512];            // pool partials

// ---------------------------------------------------------------------------
// Meta / zeropad / scatter / weight conversion
// ---------------------------------------------------------------------------
__global__ void k_meta(const int* __restrict__ idx, int N) {
    __shared__ int st[65];
    __shared__ int smax;
    int t = threadIdx.x;
    if (t == 0) smax = 0;
    if (t <= 64) {
        if (t == 64) st[64] = N;
        else {
            int lo = 0, hi = N;
            while (lo < hi) { int mid = (lo + hi) >> 1; if (idx[mid] < t) lo = mid + 1; else hi = mid; }
            st[t] = lo;
        }
    }
    __syncthreads();
    if (t < 64) {
        int c = st[t + 1] - st[t];
        g_starts[t] = st[t];
        g_counts[t] = c;
        atomicMax(&smax, c);
    }
    if (t == 64) g_starts[64] = N;
    __syncthreads();
    if (t == 0) g_maxn = (smax < CAP) ? smax : CAP;
}

__global__ void k_zeropad() {
    int g = blockIdx.x;
    int c0 = g_counts[g];
    int rows = g_maxn - c0;
    if (rows <= 0) return;
    uint4 z = make_uint4(0u, 0u, 0u, 0u);
    for (int w = threadIdx.x; w < rows * 64; w += 256) {
        int n = c0 + (w >> 6);
        int j = w & 63;
        ((uint4*)(g_Xh + (size_t)((n << 6) + g) * 512))[j] = z;
    }
}

__global__ void k_scatter(const float* __restrict__ emb, const int* __restrict__ idx) {
    int i = blockIdx.x;
    int g = idx[i];
    int n = i - g_starts[g];
    int t = threadIdx.x;
    float4 v = ((const float4*)(emb + (size_t)i * 512))[t];
    __half2* d = (__half2*)(g_Xh + (size_t)(n * 64 + g) * 512 + t * 4);
    d[0] = __floats2half2_rn(v.x, v.y);
    d[1] = __floats2half2_rn(v.z, v.w);
}

__global__ void k_cvtwA(const float* __restrict__ s, __half* __restrict__ d, int n4) {
    int i = blockIdx.x * 256 + threadIdx.x;
    if (i >= n4) return;
    float4 v = ((const float4*)s)[i];
    __half2* p = (__half2*)(d + (size_t)i * 4);
    p[0] = __floats2half2_rn(v.x, v.y);
    p[1] = __floats2half2_rn(v.z, v.w);
}

// W_o (65536 f4) | W1 (131072 f4) | W2 (131072 f4) -> g_Wh + 786432 halves
__global__ void k_cvtwB(const float* __restrict__ wo, const float* __restrict__ w1,
                        const float* __restrict__ w2, __half* __restrict__ d) {
    int i = blockIdx.x * 256 + threadIdx.x;
    if (i >= 327680) return;
    const float4* src;
    if (i < 65536)       src = (const float4*)wo + i;
    else if (i < 196608) src = (const float4*)w1 + (i - 65536);
    else                 src = (const float4*)w2 + (i - 196608);
    float4 v = *src;
    __half2* p = (__half2*)(d + (size_t)i * 4);
    p[0] = __floats2half2_rn(v.x, v.y);
    p[1] = __floats2half2_rn(v.z, v.w);
}

// ---------------------------------------------------------------------------
// fp16 mma helpers
// ---------------------------------------------------------------------------
__device__ __forceinline__ void mma_f16(float c[4],
                                        uint32_t a0, uint32_t a1, uint32_t a2, uint32_t a3,
                                        uint32_t b0, uint32_t b1) {
    asm volatile(
        "mma.sync.aligned.m16n8k16.row.col.f32.f16.f16.f32 "
        "{%0,%1,%2,%3}, {%4,%5,%6,%7}, {%8,%9}, {%0,%1,%2,%3};"
        : "+f"(c[0]), "+f"(c[1]), "+f"(c[2]), "+f"(c[3])
        : "r"(a0), "r"(a1), "r"(a2), "r"(a3), "r"(b0), "r"(b1));
}
#define LDSM4(f, a) \
    asm volatile("ldmatrix.sync.aligned.m8n8.x4.shared.b16 {%0,%1,%2,%3}, [%4];" \
                 : "=r"((f)[0]), "=r"((f)[1]), "=r"((f)[2]), "=r"((f)[3]) : "r"(a))
#define LDSM4T(f, a) \
    asm volatile("ldmatrix.sync.aligned.m8n8.x4.trans.shared.b16 {%0,%1,%2,%3}, [%4];" \
                 : "=r"((f)[0]), "=r"((f)[1]), "=r"((f)[2]), "=r"((f)[3]) : "r"(a))

__device__ __forceinline__ uint32_t packh2(float a, float b) {
    __half2 h = __floats2half2_rn(a, b);
    return *(uint32_t*)&h;
}

// ---------------------------------------------------------------------------
// fp16 tensor-core GEMM (proven R12): C = A*Bw^T + bias (+resid)(relu), fp16.
// BM=BN=128, BK=64 halves; 8 warps, warp tile 64x32; 3-stage cp.async ring.
// ---------------------------------------------------------------------------
#define SROW_H 72
#define A_BYTES (128u * SROW_H * 2u)    // 18432
#define STAGE_B (2u * A_BYTES)          // 36864
#define TG_SMEM_BYTES (3u * STAGE_B)    // 110592

__global__ __launch_bounds__(256, 2)
void k_tgemm(const __half* __restrict__ A, const __half* __restrict__ Bw,
             const float* __restrict__ bias, const __half* __restrict__ resid,
             __half* __restrict__ C, int Ncols, int K, int relu)
{
    int M = g_maxn * 64;
    int row0 = blockIdx.y * 128;
    if (row0 >= M) return;
    int col0 = blockIdx.x * 128;

    int tid  = threadIdx.x;
    int lane = tid & 31;
    int wid  = tid >> 5;
    int wm   = wid & 1;
    int wn   = wid >> 1;
    int g    = lane >> 2;
    int tg   = lane & 3;

    extern __shared__ uint32_t sm[];
    uint32_t smb = (uint32_t)__cvta_generic_to_shared(sm);

    const __half* Abase = A  + (size_t)row0 * K;
    const __half* Bbase = Bw + (size_t)col0 * K;

    int srow = tid >> 3;
    int sc8  = tid & 7;

    uint32_t rowA = (uint32_t)((wm * 64 + (lane & 15)) * SROW_H * 2);
    uint32_t kA   = (uint32_t)((lane >> 4) * 16);
    uint32_t rowB = (uint32_t)((wn * 32 + (lane & 7) + ((lane >> 3) & 1) * 8) * SROW_H * 2);
    uint32_t kB   = (uint32_t)((lane >> 4) * 16);

    float c[4][4][4];
#pragma unroll
    for (int i = 0; i < 4; i++)
#pragma unroll
        for (int j = 0; j < 4; j++)
#pragma unroll
            for (int k = 0; k < 4; k++) c[i][j][k] = 0.f;

    const int KT = K >> 6;

#define STAGE(kt_)  do {                                                          \
        int _kt = (kt_);                                                          \
        uint32_t _sb = smb + (uint32_t)(_kt % 3) * STAGE_B;                       \
        int _ko = _kt * 64 + sc8 * 8;                                             \
        _Pragma("unroll")                                                         \
        for (int _i = 0; _i < 4; _i++) {                                          \
            int _row = srow + 32 * _i;                                            \
            uint32_t _d = _sb + (uint32_t)((_row * SROW_H + sc8 * 8) * 2);        \
            int _ok = (row0 + _row) < M;                                          \
            const __half* _sa = Abase + (size_t)(_ok ? _row : 0) * K + _ko;       \
            int _sz = _ok ? 16 : 0;                                               \
            asm volatile("cp.async.cg.shared.global [%0], [%1], 16, %2;"          \
                         :: "r"(_d), "l"(_sa), "r"(_sz));                         \
            uint32_t _d2 = _d + A_BYTES;                                          \
            const __half* _sb2 = Bbase + (size_t)_row * K + _ko;                  \
            asm volatile("cp.async.cg.shared.global [%0], [%1], 16;"              \
                         :: "r"(_d2), "l"(_sb2));                                 \
        }                                                                         \
        asm volatile("cp.async.commit_group;");                                   \
    } while (0)

    STAGE(0);
    STAGE(1);

    uint32_t fa[2][4][4], fb[2][2][4];

    for (int kt = 0; kt < KT; kt++) {
        if (kt + 1 < KT) { asm volatile("cp.async.wait_group 1;"); }
        else             { asm volatile("cp.async.wait_group 0;"); }
        __syncthreads();
        if (kt + 2 < KT) STAGE(kt + 2);

        uint32_t aB = smb + (uint32_t)(kt % 3) * STAGE_B;
        uint32_t bB = aB + A_BYTES;

#pragma unroll
        for (int mt = 0; mt < 4; mt++)
            LDSM4(fa[0][mt], aB + rowA + (uint32_t)(mt * 16 * SROW_H * 2) + kA);
#pragma unroll
        for (int p = 0; p < 2; p++)
            LDSM4(fb[0][p], bB + rowB + (uint32_t)(p * 16 * SROW_H * 2) + kB);

#pragma unroll
        for (int kk = 0; kk < 4; kk++) {
            const int cb = kk & 1, nb = cb ^ 1;
            if (kk < 3) {
                uint32_t ko = (uint32_t)((kk + 1) * 32);
#pragma unroll
                for (int mt = 0; mt < 4; mt++)
                    LDSM4(fa[nb][mt], aB + rowA + (uint32_t)(mt * 16 * SROW_H * 2) + kA + ko);
#pragma unroll
                for (int p = 0; p < 2; p++)
                    LDSM4(fb[nb][p], bB + rowB + (uint32_t)(p * 16 * SROW_H * 2) + kB + ko);
            }
#pragma unroll
            for (int p = 0; p < 2; p++)
#pragma unroll
                for (int mt = 0; mt < 4; mt++) {
                    mma_f16(c[mt][2 * p],
                            fa[cb][mt][0], fa[cb][mt][1], fa[cb][mt][2], fa[cb][mt][3],
                            fb[cb][p][0], fb[cb][p][2]);
                    mma_f16(c[mt][2 * p + 1],
                            fa[cb][mt][0], fa[cb][mt][1], fa[cb][mt][2], fa[cb][mt][3],
                            fb[cb][p][1], fb[cb][p][3]);
                }
        }
    }

#pragma unroll
    for (int mt = 0; mt < 4; mt++) {
        int r0 = row0 + wm * 64 + mt * 16 + g;
        int r1 = r0 + 8;
#pragma unroll
        for (int nt = 0; nt < 4; nt++) {
            int cc = col0 + wn * 32 + nt * 8 + 2 * tg;
            float2 bv = *(const float2*)(bias + cc);
#pragma unroll
            for (int hrow = 0; hrow < 2; hrow++) {
                int r = hrow ? r1 : r0;
                if (r >= M) continue;
                float o0 = c[mt][nt][2 * hrow + 0] + bv.x;
                float o1 = c[mt][nt][2 * hrow + 1] + bv.y;
                if (resid) {
                    __half2 rv = *(const __half2*)(resid + (size_t)r * Ncols + cc);
                    float2 rf = __half22float2(rv);
                    o0 += rf.x; o1 += rf.y;
                }
                if (relu) { o0 = fmaxf(o0, 0.f); o1 = fmaxf(o1, 0.f); }
                *(__half2*)(C + (size_t)r * Ncols + cc) = __floats2half2_rn(o0, o1);
            }
        }
    }
#undef STAGE
}

// ---------------------------------------------------------------------------
// Tensor-core attention (proven R11): one block (128 thr) per (n, h).
// ---------------------------------------------------------------------------
__global__ __launch_bounds__(128)
void k_attn(const __half* __restrict__ QKVh, __half* __restrict__ ATT) {
    int n = blockIdx.x;
    if (n >= g_maxn) return;
    int h = blockIdx.y;

    __shared__ __half sQ[64 * 72];
    __shared__ __half sK[64 * 72];
    __shared__ __half sV[64 * 72];
    __shared__ int scnt[64];

    int tid  = threadIdx.x;
    int lane = tid & 31;
    int w    = tid >> 5;

    if (tid < 64) scnt[tid] = g_counts[tid];

    const __half* base = QKVh + (size_t)n * 64 * 1536 + (size_t)h * 64;
    for (int i = tid; i < 1536; i += 128) {
        int m   = i >> 9;
        int rem = i & 511;
        int row = rem >> 3;
        int c8  = rem & 7;
        const uint4* src = (const uint4*)(base + (size_t)row * 1536 + m * 512 + c8 * 8);
        __half* dstm = (m == 0) ? sQ : ((m == 1) ? sK : sV);
        *(uint4*)(dstm + row * 72 + c8 * 8) = *src;
    }
    __syncthreads();

    uint32_t qb  = (uint32_t)__cvta_generic_to_shared(sQ);
    uint32_t kb  = (uint32_t)__cvta_generic_to_shared(sK);
    uint32_t vbs = (uint32_t)__cvta_generic_to_shared(sV);

    int s0 = w * 16;
    int c2 = 2 * (lane & 3);

    int aRow = s0 + (lane & 7) + ((lane & 8) ? 8 : 0);
    int aCol = ((lane & 16) ? 8 : 0);
    int bRow = (lane & 7) + ((lane & 16) ? 8 : 0);
    int bCol = ((lane & 8) ? 8 : 0);
    int vRow = (lane & 7) + ((lane & 8) ? 8 : 0);
    int vCol = ((lane & 16) ? 8 : 0);

    float cS[8][4];
#pragma unroll
    for (int i = 0; i < 8; i++)
#pragma unroll
        for (int j = 0; j < 4; j++) cS[i][j] = 0.f;

#pragma unroll
    for (int ke = 0; ke < 4; ke++) {
        uint32_t a[4];
        LDSM4(a, qb + (uint32_t)((aRow * 72 + ke * 16 + aCol) * 2));
#pragma unroll
        for (int q = 0; q < 4; q++) {
            uint32_t b[4];
            LDSM4(b, kb + (uint32_t)(((16 * q + bRow) * 72 + ke * 16 + bCol) * 2));
            mma_f16(cS[2 * q],     a[0], a[1], a[2], a[3], b[0], b[1]);
            mma_f16(cS[2 * q + 1], a[0], a[1], a[2], a[3], b[2], b[3]);
        }
    }

#pragma unroll
    for (int hrow = 0; hrow < 2; hrow++) {
        int o = 2 * hrow;
        float mx = -1e30f;
#pragma unroll
        for (int nt = 0; nt < 8; nt++) {
#pragma unroll
            for (int e = 0; e < 2; e++) {
                int t = nt * 8 + c2 + e;
                float v = cS[nt][o + e] * 0.125f;
                if (scnt[t] <= n) v = -1e30f;
                cS[nt][o + e] = v;
                mx = fmaxf(mx, v);
            }
        }
        mx = fmaxf(mx, __shfl_xor_sync(0xffffffffu, mx, 1));
        mx = fmaxf(mx, __shfl_xor_sync(0xffffffffu, mx, 2));
        float sum = 0.f;
#pragma unroll
        for (int nt = 0; nt < 8; nt++) {
#pragma unroll
            for (int e = 0; e < 2; e++) {
                float p = __expf(cS[nt][o + e] - mx);
                cS[nt][o + e] = p;
                sum += p;
            }
        }
        sum += __shfl_xor_sync(0xffffffffu, sum, 1);
        sum += __shfl_xor_sync(0xffffffffu, sum, 2);
        float inv = 1.f / sum;
#pragma unroll
        for (int nt = 0; nt < 8; nt++) {
            cS[nt][o + 0] *= inv;
            cS[nt][o + 1] *= inv;
        }
    }

    uint32_t pa[4][4];
#pragma unroll
    for (int j = 0; j < 4; j++) {
        pa[j][0] = packh2(cS[2 * j][0],     cS[2 * j][1]);
        pa[j][1] = packh2(cS[2 * j][2],     cS[2 * j][3]);
        pa[j][2] = packh2(cS[2 * j + 1][0], cS[2 * j + 1][1]);
        pa[j][3] = packh2(cS[2 * j + 1][2], cS[2 * j + 1][3]);
    }

    float cO[8][4];
#pragma unroll
    for (int i = 0; i < 8; i++)
#pragma unroll
        for (int j = 0; j < 4; j++) cO[i][j] = 0.f;

#pragma unroll
    for (int j = 0; j < 4; j++) {
#pragma unroll
        for (int p = 0; p < 4; p++) {
            uint32_t b[4];
            LDSM4T(b, vbs + (uint32_t)(((16 * j + vRow) * 72 + p * 16 + vCol) * 2));
            mma_f16(cO[2 * p],     pa[j][0], pa[j][1], pa[j][2], pa[j][3], b[0], b[1]);
            mma_f16(cO[2 * p + 1], pa[j][0], pa[j][1], pa[j][2], pa[j][3], b[2], b[3]);
        }
    }

    int r = s0 + (lane >> 2);
#pragma unroll
    for (int nt = 0; nt < 8; nt++) {
        int col = h * 64 + nt * 8 + c2;
        uint32_t lo = packh2(cO[nt][0], cO[nt][1]);
        uint32_t hi = packh2(cO[nt][2], cO[nt][3]);
        *(uint32_t*)(ATT + (size_t)(n * 64 + r) * 512 + col)     = lo;
        *(uint32_t*)(ATT + (size_t)(n * 64 + r + 8) * 512 + col) = hi;
    }
}

// ---------------------------------------------------------------------------
// LayerNorm (LN1): 4 rows per block, 512 threads (128 per row). fp16 io.
// M is a multiple of 64 -> every block's 4 rows are uniformly valid/invalid.
// ---------------------------------------------------------------------------
__global__ __launch_bounds__(512)
void k_ln(const __half* __restrict__ in, const float* __restrict__ gam,
          const float* __restrict__ bet, __half* __restrict__ outp) {
    int r0 = blockIdx.x * 4;
    if (r0 >= g_maxn * 64) return;
    int rl = threadIdx.x >> 7;          // row within block 0..3
    int t  = threadIdx.x & 127;         // thread within row
    int r  = r0 + rl;

    const __half2* ip = (const __half2*)(in + (size_t)r * 512 + t * 4);
    float2 a = __half22float2(ip[0]);
    float2 b = __half22float2(ip[1]);
    float4 v = make_float4(a.x, a.y, b.x, b.y);
    float s  = v.x + v.y + v.z + v.w;
    float ss = fmaf(v.x, v.x, fmaf(v.y, v.y, fmaf(v.z, v.z, v.w * v.w)));
#pragma unroll
    for (int o = 16; o; o >>= 1) {
        s  += __shfl_xor_sync(0xffffffffu, s,  o);
        ss += __shfl_xor_sync(0xffffffffu, ss, o);
    }
    __shared__ float shS[16], shQ[16];
    int wir = t >> 5;                   // warp within row 0..3
    if ((t & 31) == 0) { shS[rl * 4 + wir] = s; shQ[rl * 4 + wir] = ss; }
    __syncthreads();
    s  = shS[rl * 4 + 0] + shS[rl * 4 + 1] + shS[rl * 4 + 2] + shS[rl * 4 + 3];
    ss = shQ[rl * 4 + 0] + shQ[rl * 4 + 1] + shQ[rl * 4 + 2] + shQ[rl * 4 + 3];
    float mean = s * (1.f / 512.f);
    float var  = ss * (1.f / 512.f) - mean * mean;
    float inv  = rsqrtf(var + 1e-5f);
    float4 g4 = ((const float4*)gam)[t];
    float4 b4 = ((const float4*)bet)[t];
    float o0 = (v.x - mean) * inv * g4.x + b4.x;
    float o1 = (v.y - mean) * inv * g4.y + b4.y;
    float o2 = (v.z - mean) * inv * g4.z + b4.z;
    float o3 = (v.w - mean) * inv * g4.w + b4.w;
    __half2* d = (__half2*)(outp + (size_t)r * 512 + t * 4);
    d[0] = __floats2half2_rn(o0, o1);
    d[1] = __floats2half2_rn(o2, o3);
}

// ---------------------------------------------------------------------------
// Fused LN2 + pool partials (proven R13)
// ---------------------------------------------------------------------------
__global__ __launch_bounds__(512)
void k_lnpool(const __half* __restrict__ in, const float* __restrict__ gam,
              const float* __restrict__ bet, float* __restrict__ part) {
    int chunk = blockIdx.x;
    int g     = blockIdx.y;
    int d     = threadIdx.x;
    int wid = d >> 5, lane = d & 31;

    int mx = g_maxn;
    int CH = (mx + 15) >> 4;
    int n0 = chunk * CH;
    int n1 = n0 + CH; if (n1 > mx) n1 = mx;

    __shared__ float shS[16], shQ[16], bc[2];
    float gd = gam[d], bd = bet[d];
    float acc = 0.f;

    if (n0 < n1) {
        float v = __half2float(in[(size_t)(n0 * 64 + g) * 512 + d]);
        for (int n = n0; n < n1; n++) {
            float vn = 0.f;
            if (n + 1 < n1)
                vn = __half2float(in[(size_t)((n + 1) * 64 + g) * 512 + d]);
            float s = v, ss = v * v;
#pragma unroll
            for (int o = 16; o; o >>= 1) {
                s  += __shfl_xor_sync(0xffffffffu, s,  o);
                ss += __shfl_xor_sync(0xffffffffu, ss, o);
            }
            if (lane == 0) { shS[wid] = s; shQ[wid] = ss; }
            __syncthreads();
            if (wid == 0) {
                float s2 = (lane < 16) ? shS[lane] : 0.f;
                float q2 = (lane < 16) ? shQ[lane] : 0.f;
#pragma unroll
                for (int o = 8; o; o >>= 1) {
                    s2 += __shfl_xor_sync(0xffffffffu, s2, o);
                    q2 += __shfl_xor_sync(0xffffffffu, q2, o);
                }
                if (lane == 0) { bc[0] = s2; bc[1] = q2; }
            }
            __syncthreads();
            float mean = bc[0] * (1.f / 512.f);
            float var  = bc[1] * (1.f / 512.f) - mean * mean;
            float inv  = rsqrtf(var + 1e-5f);
            acc += (v - mean) * inv * gd + bd;
            v = vn;
        }
    }
    part[(size_t)(chunk * 64 + g) * 512 + d] = acc;
}

__global__ void k_poolred(const float* __restrict__ part, float* __restrict__ out) {
    int g = blockIdx.x;
    int d = threadIdx.x;
    float s = 0.f;
#pragma unroll
    for (int c = 0; c < 16; c++)
        s += part[(size_t)(c * 64 + g) * 512 + d];
    out[g * 512 + d] = s / (float)g_maxn;
}

// ---------------------------------------------------------------------------
// Launch  (order chosen so k_tgemm is launch #6 -> ncu -s 5 -c 1 captures it)
// ---------------------------------------------------------------------------
extern "C" void kernel_launch(void* const* d_in, const int* in_sizes, int n_in,
                              void* d_out, int out_size) {
    const float* emb  = (const float*)d_in[0];
    const int*   sidx = (const int*)  d_in[1];
    const float* W_in = (const float*)d_in[2];
    const float* b_in = (const float*)d_in[3];
    const float* W_o  = (const float*)d_in[4];
    const float* b_o  = (const float*)d_in[5];
    const float* ln1g = (const float*)d_in[6];
    const float* ln1b = (const float*)d_in[7];
    const float* W1   = (const float*)d_in[8];
    const float* b1   = (const float*)d_in[9];
    const float* W2   = (const float*)d_in[10];
    const float* b2   = (const float*)d_in[11];
    const float* ln2g = (const float*)d_in[12];
    const float* ln2b = (const float*)d_in[13];
    float* out = (float*)d_out;
    (void)n_in; (void)out_size;

    int N = in_sizes[0] / 512;

    __half *pXh, *pQKVh, *pATTh, *pTMPh, *pY1h, *pHIDh, *pWh;
    float *pPART;
    cudaGetSymbolAddress((void**)&pXh,   g_Xh);
    cudaGetSymbolAddress((void**)&pQKVh, g_QKVh);
    cudaGetSymbolAddress((void**)&pATTh, g_ATTh);
    cudaGetSymbolAddress((void**)&pTMPh, g_TMPh);
    cudaGetSymbolAddress((void**)&pY1h,  g_Y1h);
    cudaGetSymbolAddress((void**)&pHIDh, g_HIDh);
    cudaGetSymbolAddress((void**)&pWh,   g_Wh);
    cudaGetSymbolAddress((void**)&pPART, g_PART);

    __half* hWin = pWh;
    __half* hWo  = pWh + 786432;

    cudaFuncSetAttribute(k_tgemm, cudaFuncAttributeMaxDynamicSharedMemorySize,
                         (int)TG_SMEM_BYTES);

    const int GY = ROWS_CAP / 128;

    k_cvtwA<<<768, 256>>>(W_in, hWin, 196608);                      // #1
    k_cvtwB<<<1280, 256>>>(W_o, W1, W2, hWo);                       // #2
    k_meta<<<1, 128>>>(sidx, N);                                    // #3
    k_zeropad<<<64, 256>>>();                                       // #4
    k_scatter<<<N, 128>>>(emb, sidx);                               // #5

    // QKV = X @ W_in^T + b_in                      [M, 1536]      // #6 (ncu)
    k_tgemm<<<dim3(12, GY), 256, TG_SMEM_BYTES>>>(pXh, hWin, b_in, nullptr,
                                                  pQKVh, 1536, 512, 0);

    // tensor-core attention                         -> ATT fp16
    k_attn<<<dim3(CAP, 8), 128>>>(pQKVh, pATTh);

    // TMP = ATT @ W_o^T + b_o + X                  [M, 512]
    k_tgemm<<<dim3(4, GY), 256, TG_SMEM_BYTES>>>(pATTh, hWo, b_o, pXh,
                                                 pTMPh, 512, 512, 0);

    // Y1 = LN1(TMP)
    k_ln<<<ROWS_CAP / 4, 512>>>(pTMPh, ln1g, ln1b, pY1h);

    // HID = relu(Y1 @ W1^T + b1)                   [M, 1024]
    k_tgemm<<<dim3(8, GY), 256, TG_SMEM_BYTES>>>(pY1h, pWh + 1048576, b1, nullptr,
                                                 pHIDh, 1024, 512, 1);

    // TMP = HID @ W2^T + b2 + Y1                   [M, 512]
    k_tgemm<<<dim3(4, GY), 256, TG_SMEM_BYTES>>>(pHIDh, pWh + 1572864, b2, pY1h,
                                                 pTMPh, 512, 1024, 0);

    // fused LN2 + pool partials, then deterministic reduce
    k_lnpool<<<dim3(16, 64), 512>>>(pTMPh, ln2g, ln2b, pPART);
    k_poolred<<<64, 512>>>(pPART, out);
}

// round 15
// speedup vs baseline: 1.0054x; 1.0054x over previous
#include <cuda_runtime.h>
#include <cuda_fp16.h>
#include <math.h>
#include <stdint.h>

// ---------------------------------------------------------------------------
// Problem: D=512, H=8 (e=64), B=64 studies, N=131072 cells.
// Padded layout: row r = n*64 + g. max_n data-dependent; CAP upper bound.
// fp16 datapath everywhere except LN stats / softmax / pool accumulation.
// ---------------------------------------------------------------------------
#define CAP       2560
#define ROWS_CAP  (CAP * 64)   // 163840

__device__ int g_maxn;
__device__ int g_starts[65];
__device__ int g_counts[64];

__device__ __align__(128) __half g_Xh  [(size_t)ROWS_CAP * 512];
__device__ __align__(128) __half g_QKVh[(size_t)ROWS_CAP * 1536];
__device__ __align__(128) __half g_ATTh[(size_t)ROWS_CAP * 512];
__device__ __align__(128) __half g_TMPh[(size_t)ROWS_CAP * 512];
__device__ __align__(128) __half g_Y1h [(size_t)ROWS_CAP * 512];
__device__ __align__(128) __half g_HIDh[(size_t)ROWS_CAP * 1024];
__device__ __align__(128) __half g_Wh  [2097152];  // fp16 W_in | W_o | W1 | W2
__device__ float g_PART[16 * 64 * 512];            // pool partials

// ---------------------------------------------------------------------------
// Meta / scatter(+zeropad) / weight conversion
// ---------------------------------------------------------------------------
__global__ void k_meta(const int* __restrict__ idx, int N) {
    __shared__ int st[65];
    __shared__ int smax;
    int t = threadIdx.x;
    if (t == 0) smax = 0;
    if (t <= 64) {
        if (t == 64) st[64] = N;
        else {
            int lo = 0, hi = N;
            while (lo < hi) { int mid = (lo + hi) >> 1; if (idx[mid] < t) lo = mid + 1; else hi = mid; }
            st[t] = lo;
        }
    }
    __syncthreads();
    if (t < 64) {
        int c = st[t + 1] - st[t];
        g_starts[t] = st[t];
        g_counts[t] = c;
        atomicMax(&smax, c);
    }
    if (t == 64) g_starts[64] = N;
    __syncthreads();
    if (t == 0) g_maxn = (smax < CAP) ? smax : CAP;
}

// blocks [0, N): scatter embedding row -> X (fp16, rounded)
// blocks [N, N+64): zero the padding rows of study (blockIdx.x - N)
__global__ void k_scatter(const float* __restrict__ emb, const int* __restrict__ idx, int N) {
    int i = blockIdx.x;
    int t = threadIdx.x;                 // 128
    if (i < N) {
        int g = idx[i];
        int n = i - g_starts[g];
        float4 v = ((const float4*)(emb + (size_t)i * 512))[t];
        __half2* d = (__half2*)(g_Xh + (size_t)(n * 64 + g) * 512 + t * 4);
        d[0] = __floats2half2_rn(v.x, v.y);
        d[1] = __floats2half2_rn(v.z, v.w);
    } else {
        int g = i - N;                   // 0..63
        int c0 = g_counts[g];
        int rows = g_maxn - c0;
        if (rows <= 0) return;
        uint4 z = make_uint4(0u, 0u, 0u, 0u);
        for (int w = t; w < rows * 64; w += 128) {
            int n = c0 + (w >> 6);
            int j = w & 63;
            ((uint4*)(g_Xh + (size_t)((n << 6) + g) * 512))[j] = z;
        }
    }
}

__global__ void k_cvtwA(const float* __restrict__ s, __half* __restrict__ d, int n4) {
    int i = blockIdx.x * 256 + threadIdx.x;
    if (i >= n4) return;
    float4 v = ((const float4*)s)[i];
    __half2* p = (__half2*)(d + (size_t)i * 4);
    p[0] = __floats2half2_rn(v.x, v.y);
    p[1] = __floats2half2_rn(v.z, v.w);
}

// W_o (65536 f4) | W1 (131072 f4) | W2 (131072 f4) -> g_Wh + 786432 halves
__global__ void k_cvtwB(const float* __restrict__ wo, const float* __restrict__ w1,
                        const float* __restrict__ w2, __half* __restrict__ d) {
    int i = blockIdx.x * 256 + threadIdx.x;
    if (i >= 327680) return;
    const float4* src;
    if (i < 65536)       src = (const float4*)wo + i;
    else if (i < 196608) src = (const float4*)w1 + (i - 65536);
    else                 src = (const float4*)w2 + (i - 196608);
    float4 v = *src;
    __half2* p = (__half2*)(d + (size_t)i * 4);
    p[0] = __floats2half2_rn(v.x, v.y);
    p[1] = __floats2half2_rn(v.z, v.w);
}

// ---------------------------------------------------------------------------
// fp16 mma helpers
// ---------------------------------------------------------------------------
__device__ __forceinline__ void mma_f16(float c[4],
                                        uint32_t a0, uint32_t a1, uint32_t a2, uint32_t a3,
                                        uint32_t b0, uint32_t b1) {
    asm volatile(
        "mma.sync.aligned.m16n8k16.row.col.f32.f16.f16.f32 "
        "{%0,%1,%2,%3}, {%4,%5,%6,%7}, {%8,%9}, {%0,%1,%2,%3};"
        : "+f"(c[0]), "+f"(c[1]), "+f"(c[2]), "+f"(c[3])
        : "r"(a0), "r"(a1), "r"(a2), "r"(a3), "r"(b0), "r"(b1));
}
#define LDSM4(f, a) \
    asm volatile("ldmatrix.sync.aligned.m8n8.x4.shared.b16 {%0,%1,%2,%3}, [%4];" \
                 : "=r"((f)[0]), "=r"((f)[1]), "=r"((f)[2]), "=r"((f)[3]) : "r"(a))
#define LDSM4T(f, a) \
    asm volatile("ldmatrix.sync.aligned.m8n8.x4.trans.shared.b16 {%0,%1,%2,%3}, [%4];" \
                 : "=r"((f)[0]), "=r"((f)[1]), "=r"((f)[2]), "=r"((f)[3]) : "r"(a))

__device__ __forceinline__ uint32_t packh2(float a, float b) {
    __half2 h = __floats2half2_rn(a, b);
    return *(uint32_t*)&h;
}

// ---------------------------------------------------------------------------
// fp16 tensor-core GEMM (proven R12): C = A*Bw^T + bias (+resid)(relu), fp16.
// BM=BN=128, BK=64 halves; 8 warps, warp tile 64x32; 3-stage cp.async ring.
// ---------------------------------------------------------------------------
#define SROW_H 72
#define A_BYTES (128u * SROW_H * 2u)    // 18432
#define STAGE_B (2u * A_BYTES)          // 36864
#define TG_SMEM_BYTES (3u * STAGE_B)    // 110592

__global__ __launch_bounds__(256, 2)
void k_tgemm(const __half* __restrict__ A, const __half* __restrict__ Bw,
             const float* __restrict__ bias, const __half* __restrict__ resid,
             __half* __restrict__ C, int Ncols, int K, int relu)
{
    int M = g_maxn * 64;
    int row0 = blockIdx.y * 128;
    if (row0 >= M) return;
    int col0 = blockIdx.x * 128;

    int tid  = threadIdx.x;
    int lane = tid & 31;
    int wid  = tid >> 5;
    int wm   = wid & 1;
    int wn   = wid >> 1;
    int g    = lane >> 2;
    int tg   = lane & 3;

    extern __shared__ uint32_t sm[];
    uint32_t smb = (uint32_t)__cvta_generic_to_shared(sm);

    const __half* Abase = A  + (size_t)row0 * K;
    const __half* Bbase = Bw + (size_t)col0 * K;

    int srow = tid >> 3;
    int sc8  = tid & 7;

    uint32_t rowA = (uint32_t)((wm * 64 + (lane & 15)) * SROW_H * 2);
    uint32_t kA   = (uint32_t)((lane >> 4) * 16);
    uint32_t rowB = (uint32_t)((wn * 32 + (lane & 7) + ((lane >> 3) & 1) * 8) * SROW_H * 2);
    uint32_t kB   = (uint32_t)((lane >> 4) * 16);

    float c[4][4][4];
#pragma unroll
    for (int i = 0; i < 4; i++)
#pragma unroll
        for (int j = 0; j < 4; j++)
#pragma unroll
            for (int k = 0; k < 4; k++) c[i][j][k] = 0.f;

    const int KT = K >> 6;

#define STAGE(kt_)  do {                                                          \
        int _kt = (kt_);                                                          \
        uint32_t _sb = smb + (uint32_t)(_kt % 3) * STAGE_B;                       \
        int _ko = _kt * 64 + sc8 * 8;                                             \
        _Pragma("unroll")                                                         \
        for (int _i = 0; _i < 4; _i++) {                                          \
            int _row = srow + 32 * _i;                                            \
            uint32_t _d = _sb + (uint32_t)((_row * SROW_H + sc8 * 8) * 2);        \
            int _ok = (row0 + _row) < M;                                          \
            const __half* _sa = Abase + (size_t)(_ok ? _row : 0) * K + _ko;       \
            int _sz = _ok ? 16 : 0;                                               \
            asm volatile("cp.async.cg.shared.global [%0], [%1], 16, %2;"          \
                         :: "r"(_d), "l"(_sa), "r"(_sz));                         \
            uint32_t _d2 = _d + A_BYTES;                                          \
            const __half* _sb2 = Bbase + (size_t)_row * K + _ko;                  \
            asm volatile("cp.async.cg.shared.global [%0], [%1], 16;"              \
                         :: "r"(_d2), "l"(_sb2));                                 \
        }                                                                         \
        asm volatile("cp.async.commit_group;");                                   \
    } while (0)

    STAGE(0);
    STAGE(1);

    uint32_t fa[2][4][4], fb[2][2][4];

    for (int kt = 0; kt < KT; kt++) {
        if (kt + 1 < KT) { asm volatile("cp.async.wait_group 1;"); }
        else             { asm volatile("cp.async.wait_group 0;"); }
        __syncthreads();
        if (kt + 2 < KT) STAGE(kt + 2);

        uint32_t aB = smb + (uint32_t)(kt % 3) * STAGE_B;
        uint32_t bB = aB + A_BYTES;

#pragma unroll
        for (int mt = 0; mt < 4; mt++)
            LDSM4(fa[0][mt], aB + rowA + (uint32_t)(mt * 16 * SROW_H * 2) + kA);
#pragma unroll
        for (int p = 0; p < 2; p++)
            LDSM4(fb[0][p], bB + rowB + (uint32_t)(p * 16 * SROW_H * 2) + kB);

#pragma unroll
        for (int kk = 0; kk < 4; kk++) {
            const int cb = kk & 1, nb = cb ^ 1;
            if (kk < 3) {
                uint32_t ko = (uint32_t)((kk + 1) * 32);
#pragma unroll
                for (int mt = 0; mt < 4; mt++)
                    LDSM4(fa[nb][mt], aB + rowA + (uint32_t)(mt * 16 * SROW_H * 2) + kA + ko);
#pragma unroll
                for (int p = 0; p < 2; p++)
                    LDSM4(fb[nb][p], bB + rowB + (uint32_t)(p * 16 * SROW_H * 2) + kB + ko);
            }
#pragma unroll
            for (int p = 0; p < 2; p++)
#pragma unroll
                for (int mt = 0; mt < 4; mt++) {
                    mma_f16(c[mt][2 * p],
                            fa[cb][mt][0], fa[cb][mt][1], fa[cb][mt][2], fa[cb][mt][3],
                            fb[cb][p][0], fb[cb][p][2]);
                    mma_f16(c[mt][2 * p + 1],
                            fa[cb][mt][0], fa[cb][mt][1], fa[cb][mt][2], fa[cb][mt][3],
                            fb[cb][p][1], fb[cb][p][3]);
                }
        }
    }

#pragma unroll
    for (int mt = 0; mt < 4; mt++) {
        int r0 = row0 + wm * 64 + mt * 16 + g;
        int r1 = r0 + 8;
#pragma unroll
        for (int nt = 0; nt < 4; nt++) {
            int cc = col0 + wn * 32 + nt * 8 + 2 * tg;
            float2 bv = *(const float2*)(bias + cc);
#pragma unroll
            for (int hrow = 0; hrow < 2; hrow++) {
                int r = hrow ? r1 : r0;
                if (r >= M) continue;
                float o0 = c[mt][nt][2 * hrow + 0] + bv.x;
                float o1 = c[mt][nt][2 * hrow + 1] + bv.y;
                if (resid) {
                    __half2 rv = *(const __half2*)(resid + (size_t)r * Ncols + cc);
                    float2 rf = __half22float2(rv);
                    o0 += rf.x; o1 += rf.y;
                }
                if (relu) { o0 = fmaxf(o0, 0.f); o1 = fmaxf(o1, 0.f); }
                *(__half2*)(C + (size_t)r * Ncols + cc) = __floats2half2_rn(o0, o1);
            }
        }
    }
#undef STAGE
}

// ---------------------------------------------------------------------------
// Tensor-core attention (proven R11): one block (128 thr) per (n, h).
// ---------------------------------------------------------------------------
__global__ __launch_bounds__(128)
void k_attn(const __half* __restrict__ QKVh, __half* __restrict__ ATT) {
    int n = blockIdx.x;
    if (n >= g_maxn) return;
    int h = blockIdx.y;

    __shared__ __half sQ[64 * 72];
    __shared__ __half sK[64 * 72];
    __shared__ __half sV[64 * 72];
    __shared__ int scnt[64];

    int tid  = threadIdx.x;
    int lane = tid & 31;
    int w    = tid >> 5;

    if (tid < 64) scnt[tid] = g_counts[tid];

    const __half* base = QKVh + (size_t)n * 64 * 1536 + (size_t)h * 64;
    for (int i = tid; i < 1536; i += 128) {
        int m   = i >> 9;
        int rem = i & 511;
        int row = rem >> 3;
        int c8  = rem & 7;
        const uint4* src = (const uint4*)(base + (size_t)row * 1536 + m * 512 + c8 * 8);
        __half* dstm = (m == 0) ? sQ : ((m == 1) ? sK : sV);
        *(uint4*)(dstm + row * 72 + c8 * 8) = *src;
    }
    __syncthreads();

    uint32_t qb  = (uint32_t)__cvta_generic_to_shared(sQ);
    uint32_t kb  = (uint32_t)__cvta_generic_to_shared(sK);
    uint32_t vbs = (uint32_t)__cvta_generic_to_shared(sV);

    int s0 = w * 16;
    int c2 = 2 * (lane & 3);

    int aRow = s0 + (lane & 7) + ((lane & 8) ? 8 : 0);
    int aCol = ((lane & 16) ? 8 : 0);
    int bRow = (lane & 7) + ((lane & 16) ? 8 : 0);
    int bCol = ((lane & 8) ? 8 : 0);
    int vRow = (lane & 7) + ((lane & 8) ? 8 : 0);
    int vCol = ((lane & 16) ? 8 : 0);

    float cS[8][4];
#pragma unroll
    for (int i = 0; i < 8; i++)
#pragma unroll
        for (int j = 0; j < 4; j++) cS[i][j] = 0.f;

#pragma unroll
    for (int ke = 0; ke < 4; ke++) {
        uint32_t a[4];
        LDSM4(a, qb + (uint32_t)((aRow * 72 + ke * 16 + aCol) * 2));
#pragma unroll
        for (int q = 0; q < 4; q++) {
            uint32_t b[4];
            LDSM4(b, kb + (uint32_t)(((16 * q + bRow) * 72 + ke * 16 + bCol) * 2));
            mma_f16(cS[2 * q],     a[0], a[1], a[2], a[3], b[0], b[1]);
            mma_f16(cS[2 * q + 1], a[0], a[1], a[2], a[3], b[2], b[3]);
        }
    }

#pragma unroll
    for (int hrow = 0; hrow < 2; hrow++) {
        int o = 2 * hrow;
        float mx = -1e30f;
#pragma unroll
        for (int nt = 0; nt < 8; nt++) {
#pragma unroll
            for (int e = 0; e < 2; e++) {
                int t = nt * 8 + c2 + e;
                float v = cS[nt][o + e] * 0.125f;
                if (scnt[t] <= n) v = -1e30f;
                cS[nt][o + e] = v;
                mx = fmaxf(mx, v);
            }
        }
        mx = fmaxf(mx, __shfl_xor_sync(0xffffffffu, mx, 1));
        mx = fmaxf(mx, __shfl_xor_sync(0xffffffffu, mx, 2));
        float sum = 0.f;
#pragma unroll
        for (int nt = 0; nt < 8; nt++) {
#pragma unroll
            for (int e = 0; e < 2; e++) {
                float p = __expf(cS[nt][o + e] - mx);
                cS[nt][o + e] = p;
                sum += p;
            }
        }
        sum += __shfl_xor_sync(0xffffffffu, sum, 1);
        sum += __shfl_xor_sync(0xffffffffu, sum, 2);
        float inv = 1.f / sum;
#pragma unroll
        for (int nt = 0; nt < 8; nt++) {
            cS[nt][o + 0] *= inv;
            cS[nt][o + 1] *= inv;
        }
    }

    uint32_t pa[4][4];
#pragma unroll
    for (int j = 0; j < 4; j++) {
        pa[j][0] = packh2(cS[2 * j][0],     cS[2 * j][1]);
        pa[j][1] = packh2(cS[2 * j][2],     cS[2 * j][3]);
        pa[j][2] = packh2(cS[2 * j + 1][0], cS[2 * j + 1][1]);
        pa[j][3] = packh2(cS[2 * j + 1][2], cS[2 * j + 1][3]);
    }

    float cO[8][4];
#pragma unroll
    for (int i = 0; i < 8; i++)
#pragma unroll
        for (int j = 0; j < 4; j++) cO[i][j] = 0.f;

#pragma unroll
    for (int j = 0; j < 4; j++) {
#pragma unroll
        for (int p = 0; p < 4; p++) {
            uint32_t b[4];
            LDSM4T(b, vbs + (uint32_t)(((16 * j + vRow) * 72 + p * 16 + vCol) * 2));
            mma_f16(cO[2 * p],     pa[j][0], pa[j][1], pa[j][2], pa[j][3], b[0], b[1]);
            mma_f16(cO[2 * p + 1], pa[j][0], pa[j][1], pa[j][2], pa[j][3], b[2], b[3]);
        }
    }

    int r = s0 + (lane >> 2);
#pragma unroll
    for (int nt = 0; nt < 8; nt++) {
        int col = h * 64 + nt * 8 + c2;
        uint32_t lo = packh2(cO[nt][0], cO[nt][1]);
        uint32_t hi = packh2(cO[nt][2], cO[nt][3]);
        *(uint32_t*)(ATT + (size_t)(n * 64 + r) * 512 + col)     = lo;
        *(uint32_t*)(ATT + (size_t)(n * 64 + r + 8) * 512 + col) = hi;
    }
}

// ---------------------------------------------------------------------------
// LayerNorm (LN1, proven R13): fp16 in/out, fp32 stats, 128 threads/row.
// ---------------------------------------------------------------------------
__global__ void k_ln(const __half* __restrict__ in, const float* __restrict__ gam,
                     const float* __restrict__ bet, __half* __restrict__ outp) {
    int r = blockIdx.x;
    if (r >= g_maxn * 64) return;
    int t = threadIdx.x;
    const __half2* ip = (const __half2*)(in + (size_t)r * 512 + t * 4);
    float2 a = __half22float2(ip[0]);
    float2 b = __half22float2(ip[1]);
    float4 v = make_float4(a.x, a.y, b.x, b.y);
    float s  = v.x + v.y + v.z + v.w;
    float ss = fmaf(v.x, v.x, fmaf(v.y, v.y, fmaf(v.z, v.z, v.w * v.w)));
#pragma unroll
    for (int o = 16; o; o >>= 1) {
        s  += __shfl_xor_sync(0xffffffffu, s,  o);
        ss += __shfl_xor_sync(0xffffffffu, ss, o);
    }
    __shared__ float sh[8];
    if ((t & 31) == 0) { sh[t >> 5] = s; sh[4 + (t >> 5)] = ss; }
    __syncthreads();
    s  = sh[0] + sh[1] + sh[2] + sh[3];
    ss = sh[4] + sh[5] + sh[6] + sh[7];
    float mean = s * (1.f / 512.f);
    float var  = ss * (1.f / 512.f) - mean * mean;
    float inv  = rsqrtf(var + 1e-5f);
    float4 g4 = ((const float4*)gam)[t];
    float4 b4 = ((const float4*)bet)[t];
    float o0 = (v.x - mean) * inv * g4.x + b4.x;
    float o1 = (v.y - mean) * inv * g4.y + b4.y;
    float o2 = (v.z - mean) * inv * g4.z + b4.z;
    float o3 = (v.w - mean) * inv * g4.w + b4.w;
    __half2* d = (__half2*)(outp + (size_t)r * 512 + t * 4);
    d[0] = __floats2half2_rn(o0, o1);
    d[1] = __floats2half2_rn(o2, o3);
}

// ---------------------------------------------------------------------------
// Fused LN2 + pool partials (proven R13)
// ---------------------------------------------------------------------------
__global__ __launch_bounds__(512)
void k_lnpool(const __half* __restrict__ in, const float* __restrict__ gam,
              const float* __restrict__ bet, float* __restrict__ part) {
    int chunk = blockIdx.x;
    int g     = blockIdx.y;
    int d     = threadIdx.x;
    int wid = d >> 5, lane = d & 31;

    int mx = g_maxn;
    int CH = (mx + 15) >> 4;
    int n0 = chunk * CH;
    int n1 = n0 + CH; if (n1 > mx) n1 = mx;

    __shared__ float shS[16], shQ[16], bc[2];
    float gd = gam[d], bd = bet[d];
    float acc = 0.f;

    if (n0 < n1) {
        float v = __half2float(in[(size_t)(n0 * 64 + g) * 512 + d]);
        for (int n = n0; n < n1; n++) {
            float vn = 0.f;
            if (n + 1 < n1)
                vn = __half2float(in[(size_t)((n + 1) * 64 + g) * 512 + d]);
            float s = v, ss = v * v;
#pragma unroll
            for (int o = 16; o; o >>= 1) {
                s  += __shfl_xor_sync(0xffffffffu, s,  o);
                ss += __shfl_xor_sync(0xffffffffu, ss, o);
            }
            if (lane == 0) { shS[wid] = s; shQ[wid] = ss; }
            __syncthreads();
            if (wid == 0) {
                float s2 = (lane < 16) ? shS[lane] : 0.f;
                float q2 = (lane < 16) ? shQ[lane] : 0.f;
#pragma unroll
                for (int o = 8; o; o >>= 1) {
                    s2 += __shfl_xor_sync(0xffffffffu, s2, o);
                    q2 += __shfl_xor_sync(0xffffffffu, q2, o);
                }
                if (lane == 0) { bc[0] = s2; bc[1] = q2; }
            }
            __syncthreads();
            float mean = bc[0] * (1.f / 512.f);
            float var  = bc[1] * (1.f / 512.f) - mean * mean;
            float inv  = rsqrtf(var + 1e-5f);
            acc += (v - mean) * inv * gd + bd;
            v = vn;
        }
    }
    part[(size_t)(chunk * 64 + g) * 512 + d] = acc;
}

__global__ void k_poolred(const float* __restrict__ part, float* __restrict__ out) {
    int g = blockIdx.x;
    int d = threadIdx.x;
    float s = 0.f;
#pragma unroll
    for (int c = 0; c < 16; c++)
        s += part[(size_t)(c * 64 + g) * 512 + d];
    out[g * 512 + d] = s / (float)g_maxn;
}

// ---------------------------------------------------------------------------
// Launch  (harness issues 2 internal launches; ncu -s5 -c1 captures OUR #4
//          -> k_tgemm is placed at our launch #4)
// ---------------------------------------------------------------------------
extern "C" void kernel_launch(void* const* d_in, const int* in_sizes, int n_in,
                              void* d_out, int out_size) {
    const float* emb  = (const float*)d_in[0];
    const int*   sidx = (const int*)  d_in[1];
    const float* W_in = (const float*)d_in[2];
    const float* b_in = (const float*)d_in[3];
    const float* W_o  = (const float*)d_in[4];
    const float* b_o  = (const float*)d_in[5];
    const float* ln1g = (const float*)d_in[6];
    const float* ln1b = (const float*)d_in[7];
    const float* W1   = (const float*)d_in[8];
    const float* b1   = (const float*)d_in[9];
    const float* W2   = (const float*)d_in[10];
    const float* b2   = (const float*)d_in[11];
    const float* ln2g = (const float*)d_in[12];
    const float* ln2b = (const float*)d_in[13];
    float* out = (float*)d_out;
    (void)n_in; (void)out_size;

    int N = in_sizes[0] / 512;

    __half *pXh, *pQKVh, *pATTh, *pTMPh, *pY1h, *pHIDh, *pWh;
    float *pPART;
    cudaGetSymbolAddress((void**)&pXh,   g_Xh);
    cudaGetSymbolAddress((void**)&pQKVh, g_QKVh);
    cudaGetSymbolAddress((void**)&pATTh, g_ATTh);
    cudaGetSymbolAddress((void**)&pTMPh, g_TMPh);
    cudaGetSymbolAddress((void**)&pY1h,  g_Y1h);
    cudaGetSymbolAddress((void**)&pHIDh, g_HIDh);
    cudaGetSymbolAddress((void**)&pWh,   g_Wh);
    cudaGetSymbolAddress((void**)&pPART, g_PART);

    __half* hWin = pWh;
    __half* hWo  = pWh + 786432;

    cudaFuncSetAttribute(k_tgemm, cudaFuncAttributeMaxDynamicSharedMemorySize,
                         (int)TG_SMEM_BYTES);

    const int GY = ROWS_CAP / 128;

    k_cvtwA<<<768, 256>>>(W_in, hWin, 196608);                      // our #1
    k_meta<<<1, 128>>>(sidx, N);                                    // our #2
    k_scatter<<<N + 64, 128>>>(emb, sidx, N);                       // our #3

    // QKV = X @ W_in^T + b_in                      [M, 1536]      // our #4 (ncu)
    k_tgemm<<<dim3(12, GY), 256, TG_SMEM_BYTES>>>(pXh, hWin, b_in, nullptr,
                                                  pQKVh, 1536, 512, 0);

    k_cvtwB<<<1280, 256>>>(W_o, W1, W2, hWo);                       // our #5

    // tensor-core attention                         -> ATT fp16
    k_attn<<<dim3(CAP, 8), 128>>>(pQKVh, pATTh);

    // TMP = ATT @ W_o^T + b_o + X                  [M, 512]
    k_tgemm<<<dim3(4, GY), 256, TG_SMEM_BYTES>>>(pATTh, hWo, b_o, pXh,
                                                 pTMPh, 512, 512, 0);

    // Y1 = LN1(TMP)
    k_ln<<<ROWS_CAP, 128>>>(pTMPh, ln1g, ln1b, pY1h);

    // HID = relu(Y1 @ W1^T + b1)                   [M, 1024]
    k_tgemm<<<dim3(8, GY), 256, TG_SMEM_BYTES>>>(pY1h, pWh + 1048576, b1, nullptr,
                                                 pHIDh, 1024, 512, 1);

    // TMP = HID @ W2^T + b2 + Y1                   [M, 512]
    k_tgemm<<<dim3(4, GY), 256, TG_SMEM_BYTES>>>(pHIDh, pWh + 1572864, b2, pY1h,
                                                 pTMPh, 512, 1024, 0);

    // fused LN2 + pool partials, then deterministic reduce
    k_lnpool<<<dim3(16, 64), 512>>>(pTMPh, ln2g, ln2b, pPART);
    k_poolred<<<64, 512>>>(pPART, out);
}